// round 2
// baseline (speedup 1.0000x reference)
#include <cuda_runtime.h>
#include <cuda_bf16.h>

// Problem constants
#define TRAJ      25      // trajectories per outer
#define NT        10      // mid-segment time samples (EVAL_POINTS//3)
#define NS        10      // line-of-sight samples (NUM_LOS)
#define GDIM      200     // voxel grid per axis
#define MAP_ELEMS 8000000 // 200^3
#define VFOV_C    0.3490658503988659f   // deg2rad(20)

// Inputs (metadata order): Df [B,3,3], Dp [B,3,3], goal [B,3], L [6,6],
// sdf_maps [M,200,200,200], min_bounds [M,3], map_id [OUTER] int32
// Output: float32 [B], B = OUTER*25

// One block per trajectory. 128 threads; threads 0..99 each handle one
// (t, s) sample pair. Maximizes warp count to hide scattered-gather latency.
__global__ __launch_bounds__(128) void track_loss_kernel(
    const float* __restrict__ Df, const float* __restrict__ Dp,
    const float* __restrict__ goal, const float* __restrict__ L,
    const float* __restrict__ sdf, const float* __restrict__ minb,
    const int*   __restrict__ map_id, float* __restrict__ out)
{
    const int b   = blockIdx.x;        // trajectory index [0, B)
    const int o   = b / TRAJ;          // outer group
    const int tid = threadIdx.x;

    float contrib = 0.0f;

    if (tid < NT * NS) {
        const int it = tid / NS;       // time sample
        const int s  = tid - it * NS;  // LOS sample

        // --- quintic coefficients: coe[c][i] = sum_j L[i][j] * d[c][j] ---
        // (redundant per thread; FMA pipe is idle, loads broadcast from L1)
        float coe[3][6];
        #pragma unroll
        for (int c = 0; c < 3; c++) {
            const float d0 = __ldg(Df + b * 9 + c * 3 + 0);
            const float d1 = __ldg(Df + b * 9 + c * 3 + 1);
            const float d2 = __ldg(Df + b * 9 + c * 3 + 2);
            const float d3 = __ldg(Dp + b * 9 + c * 3 + 0);
            const float d4 = __ldg(Dp + b * 9 + c * 3 + 1);
            const float d5 = __ldg(Dp + b * 9 + c * 3 + 2);
            #pragma unroll
            for (int i = 0; i < 6; i++) {
                coe[c][i] = __ldg(L + i * 6 + 0) * d0 + __ldg(L + i * 6 + 1) * d1
                          + __ldg(L + i * 6 + 2) * d2 + __ldg(L + i * 6 + 3) * d3
                          + __ldg(L + i * 6 + 4) * d4 + __ldg(L + i * 6 + 5) * d5;
            }
        }

        // t = linspace(0.66, 1.32, 10)[it]
        const float t = 0.66f + (float)it * ((1.32f - 0.66f) / 9.0f);

        // position (quintic), Horner
        float pos[3];
        #pragma unroll
        for (int c = 0; c < 3; c++) {
            float p = coe[c][5];
            p = p * t + coe[c][4];
            p = p * t + coe[c][3];
            p = p * t + coe[c][2];
            p = p * t + coe[c][1];
            p = p * t + coe[c][0];
            pos[c] = p;
        }

        // goal of the first trajectory in this outer group
        const float gx0 = __ldg(goal + (long long)o * TRAJ * 3 + 0);
        const float gy0 = __ldg(goal + (long long)o * TRAJ * 3 + 1);
        const float gz0 = __ldg(goal + (long long)o * TRAJ * 3 + 2);

        const float gdx = gx0 - pos[0];
        const float gdy = gy0 - pos[1];
        const float gdz = gz0 - pos[2];

        // --- pitch penalty: once per (b, t), on the s==0 thread ---
        if (s == 0) {
            float vel[3];
            #pragma unroll
            for (int c = 0; c < 3; c++) {
                float v = 5.0f * coe[c][5];
                v = v * t + 4.0f * coe[c][4];
                v = v * t + 3.0f * coe[c][3];
                v = v * t + 2.0f * coe[c][2];
                v = v * t + coe[c][1];
                vel[c] = v;
            }
            const float pg = atan2f(gdz, sqrtf(gdx * gdx + gdy * gdy + 1e-6f));
            const float pv = atan2f(vel[2], sqrtf(vel[0] * vel[0] + vel[1] * vel[1] + 1e-6f));
            const float pen = fmaxf(fabsf(pg - pv) - VFOV_C, 0.0f);
            contrib += pen * (1.0f / (float)NT);
        }

        // --- occlusion sample: trilinear SDF lookup at LOS point s ---
        const int   m   = __ldg(map_id + o);
        const float mb0 = __ldg(minb + m * 3 + 0);
        const float mb1 = __ldg(minb + m * 3 + 1);
        const float mb2 = __ldg(minb + m * 3 + 2);
        const float* __restrict__ map = sdf + (long long)m * MAP_ELEMS;

        const float a  = (float)s * (1.0f / 9.0f);
        const float vx = (pos[0] + a * gdx - mb0) * 5.0f;   // /0.2
        const float vy = (pos[1] + a * gdy - mb1) * 5.0f;
        const float vz = (pos[2] + a * gdz - mb2) * 5.0f;

        const bool valid = (vx > 0.5f) && (vx < (float)GDIM - 1.5f)
                        && (vy > 0.5f) && (vy < (float)GDIM - 1.5f)
                        && (vz > 0.5f) && (vz < (float)GDIM - 1.5f);

        float cost = 0.0f;   // invalid -> cost 0 -> relu(0.2-0)=0.2 contribution
        if (valid) {
            const float x0f = fminf(fmaxf(floorf(vx), 0.0f), (float)(GDIM - 2));
            const float y0f = fminf(fmaxf(floorf(vy), 0.0f), (float)(GDIM - 2));
            const float z0f = fminf(fmaxf(floorf(vz), 0.0f), (float)(GDIM - 2));
            const float fx = vx - x0f, fy = vy - y0f, fz = vz - z0f;
            const int ix = (int)x0f, iy = (int)y0f, iz = (int)z0f;
            const int base = iz * (GDIM * GDIM) + iy * GDIM + ix;

            const float c000 = __ldg(map + base);
            const float c001 = __ldg(map + base + 1);
            const float c010 = __ldg(map + base + GDIM);
            const float c011 = __ldg(map + base + GDIM + 1);
            const float c100 = __ldg(map + base + GDIM * GDIM);
            const float c101 = __ldg(map + base + GDIM * GDIM + 1);
            const float c110 = __ldg(map + base + GDIM * GDIM + GDIM);
            const float c111 = __ldg(map + base + GDIM * GDIM + GDIM + 1);

            const float omx = 1.0f - fx, omy = 1.0f - fy;
            const float c0 = (c000 * omx + c001 * fx) * omy
                           + (c010 * omx + c011 * fx) * fy;
            const float c1 = (c100 * omx + c101 * fx) * omy
                           + (c110 * omx + c111 * fx) * fy;
            const float dist = c0 * (1.0f - fz) + c1 * fz;
            cost = __expf(-(dist - 0.6f) * (1.0f / 0.3f));
        }
        // occlusion contribution: relu * 4 / (NS*NT)
        contrib += fmaxf(0.2f - cost, 0.0f) * (4.0f / (float)(NS * NT));
    }

    // --- block reduction: 4 warps -> 4 partials -> final ---
    __shared__ float sPart[4];
    #pragma unroll
    for (int off = 16; off > 0; off >>= 1)
        contrib += __shfl_down_sync(0xFFFFFFFFu, contrib, off);

    const int wid = tid >> 5;
    const int lid = tid & 31;
    if (lid == 0) sPart[wid] = contrib;
    __syncthreads();

    if (tid == 0) {
        const float total = sPart[0] + sPart[1] + sPart[2] + sPart[3];
        out[b] = total * 5.0f;
    }
}

extern "C" void kernel_launch(void* const* d_in, const int* in_sizes, int n_in,
                              void* d_out, int out_size)
{
    const float* Df     = (const float*)d_in[0];
    const float* Dp     = (const float*)d_in[1];
    const float* goal   = (const float*)d_in[2];
    const float* L      = (const float*)d_in[3];
    const float* sdf    = (const float*)d_in[4];
    const float* minb   = (const float*)d_in[5];
    const int*   map_id = (const int*)d_in[6];
    float* out = (float*)d_out;

    const int outer = in_sizes[6];   // number of outer groups (map_id count)
    const int B = outer * TRAJ;

    track_loss_kernel<<<B, 128>>>(Df, Dp, goal, L, sdf, minb, map_id, out);
}

// round 3
// speedup vs baseline: 1.0341x; 1.0341x over previous
#include <cuda_runtime.h>
#include <cuda_bf16.h>

#define TRAJ      25
#define NT        10
#define NS        10
#define GDIM      200
#define MAP_ELEMS 8000000
#define VFOV_C    0.3490658503988659f

// Inputs: Df [B,3,3], Dp [B,3,3], goal [B,3], L [6,6],
// sdf_maps [M,200,200,200], min_bounds [M,3], map_id [OUTER] int32
// Output: float32 [B], B = OUTER*25
//
// Grid: (outer, NT). Each block handles one (outer group, time sample):
//   phase 1: threads 0..24 compute prelude once per trajectory
//   phase 2: threads 0..249 each do ONE trilinear SDF sample
//   per-traj partial -> atomicAdd into out (10 partials per output)

__global__ void zero_out_kernel(float* __restrict__ out, int n)
{
    int i = blockIdx.x * blockDim.x + threadIdx.x;
    if (i < n) out[i] = 0.0f;
}

__global__ __launch_bounds__(256) void track_loss_kernel(
    const float* __restrict__ Df, const float* __restrict__ Dp,
    const float* __restrict__ goal, const float* __restrict__ L,
    const float* __restrict__ sdf, const float* __restrict__ minb,
    const int*   __restrict__ map_id, float* __restrict__ out)
{
    const int o   = blockIdx.x;    // outer group
    const int it  = blockIdx.y;    // time sample index
    const int tid = threadIdx.x;

    __shared__ float sL[36];
    __shared__ float sPos[TRAJ][3];
    __shared__ float sGd[TRAJ][3];
    __shared__ float sPen[TRAJ];
    __shared__ float sC[TRAJ * NS];
    __shared__ float sG[3];
    __shared__ float sMb[3];
    __shared__ int   sMap;

    if (tid < 36) sL[tid] = L[tid];
    if (tid == 0) {
        int m = map_id[o];
        sMap  = m;
        sMb[0] = minb[m * 3 + 0];
        sMb[1] = minb[m * 3 + 1];
        sMb[2] = minb[m * 3 + 2];
        sG[0] = goal[(long long)o * TRAJ * 3 + 0];
        sG[1] = goal[(long long)o * TRAJ * 3 + 1];
        sG[2] = goal[(long long)o * TRAJ * 3 + 2];
    }
    __syncthreads();

    // ---- phase 1: prelude, once per trajectory (this block's fixed t) ----
    if (tid < TRAJ) {
        const int b = o * TRAJ + tid;
        const float t = 0.66f + (float)it * ((1.32f - 0.66f) / 9.0f);

        float pos[3], vel[3];
        #pragma unroll
        for (int c = 0; c < 3; c++) {
            const float d0 = __ldg(Df + b * 9 + c * 3 + 0);
            const float d1 = __ldg(Df + b * 9 + c * 3 + 1);
            const float d2 = __ldg(Df + b * 9 + c * 3 + 2);
            const float d3 = __ldg(Dp + b * 9 + c * 3 + 0);
            const float d4 = __ldg(Dp + b * 9 + c * 3 + 1);
            const float d5 = __ldg(Dp + b * 9 + c * 3 + 2);
            float coe[6];
            #pragma unroll
            for (int i = 0; i < 6; i++) {
                coe[i] = sL[i * 6 + 0] * d0 + sL[i * 6 + 1] * d1
                       + sL[i * 6 + 2] * d2 + sL[i * 6 + 3] * d3
                       + sL[i * 6 + 4] * d4 + sL[i * 6 + 5] * d5;
            }
            float p = coe[5];
            p = p * t + coe[4];
            p = p * t + coe[3];
            p = p * t + coe[2];
            p = p * t + coe[1];
            p = p * t + coe[0];
            pos[c] = p;
            float v = 5.0f * coe[5];
            v = v * t + 4.0f * coe[4];
            v = v * t + 3.0f * coe[3];
            v = v * t + 2.0f * coe[2];
            v = v * t + coe[1];
            vel[c] = v;
        }

        const float gdx = sG[0] - pos[0];
        const float gdy = sG[1] - pos[1];
        const float gdz = sG[2] - pos[2];

        sPos[tid][0] = pos[0]; sPos[tid][1] = pos[1]; sPos[tid][2] = pos[2];
        sGd[tid][0]  = gdx;    sGd[tid][1]  = gdy;    sGd[tid][2]  = gdz;

        const float pg = atan2f(gdz, sqrtf(gdx * gdx + gdy * gdy + 1e-6f));
        const float pv = atan2f(vel[2], sqrtf(vel[0] * vel[0] + vel[1] * vel[1] + 1e-6f));
        sPen[tid] = fmaxf(fabsf(pg - pv) - VFOV_C, 0.0f);
    }
    __syncthreads();

    // ---- phase 2: one trilinear SDF sample per thread ----
    if (tid < TRAJ * NS) {
        const int j = tid / NS;        // trajectory
        const int s = tid - j * NS;    // LOS sample

        const float a  = (float)s * (1.0f / 9.0f);
        const float vx = (sPos[j][0] + a * sGd[j][0] - sMb[0]) * 5.0f;
        const float vy = (sPos[j][1] + a * sGd[j][1] - sMb[1]) * 5.0f;
        const float vz = (sPos[j][2] + a * sGd[j][2] - sMb[2]) * 5.0f;

        const bool valid = (vx > 0.5f) && (vx < (float)GDIM - 1.5f)
                        && (vy > 0.5f) && (vy < (float)GDIM - 1.5f)
                        && (vz > 0.5f) && (vz < (float)GDIM - 1.5f);

        float cost = 0.0f;  // invalid -> relu(0.2-0)=0.2 contribution
        if (valid) {
            const float* __restrict__ map = sdf + (long long)sMap * MAP_ELEMS;
            const float x0f = fminf(fmaxf(floorf(vx), 0.0f), (float)(GDIM - 2));
            const float y0f = fminf(fmaxf(floorf(vy), 0.0f), (float)(GDIM - 2));
            const float z0f = fminf(fmaxf(floorf(vz), 0.0f), (float)(GDIM - 2));
            const float fx = vx - x0f, fy = vy - y0f, fz = vz - z0f;
            const int ix = (int)x0f, iy = (int)y0f, iz = (int)z0f;
            const int base = iz * (GDIM * GDIM) + iy * GDIM + ix;

            const float c000 = __ldg(map + base);
            const float c001 = __ldg(map + base + 1);
            const float c010 = __ldg(map + base + GDIM);
            const float c011 = __ldg(map + base + GDIM + 1);
            const float c100 = __ldg(map + base + GDIM * GDIM);
            const float c101 = __ldg(map + base + GDIM * GDIM + 1);
            const float c110 = __ldg(map + base + GDIM * GDIM + GDIM);
            const float c111 = __ldg(map + base + GDIM * GDIM + GDIM + 1);

            const float omx = 1.0f - fx, omy = 1.0f - fy;
            const float c0 = (c000 * omx + c001 * fx) * omy
                           + (c010 * omx + c011 * fx) * fy;
            const float c1 = (c100 * omx + c101 * fx) * omy
                           + (c110 * omx + c111 * fx) * fy;
            const float dist = c0 * (1.0f - fz) + c1 * fz;
            cost = __expf(-(dist - 0.6f) * (1.0f / 0.3f));
        }
        // scaled occlusion contribution:
        // out = 0.2 * sum_{t,s} w + 0.5 * sum_t pen, this block covers one t
        sC[tid] = 0.2f * fmaxf(0.2f - cost, 0.0f);
    }
    __syncthreads();

    // ---- per-trajectory partial -> global atomic accumulate ----
    if (tid < TRAJ) {
        float v = 0.5f * sPen[tid];
        #pragma unroll
        for (int k = 0; k < NS; k++) v += sC[tid * NS + k];
        atomicAdd(&out[o * TRAJ + tid], v);
    }
}

extern "C" void kernel_launch(void* const* d_in, const int* in_sizes, int n_in,
                              void* d_out, int out_size)
{
    const float* Df     = (const float*)d_in[0];
    const float* Dp     = (const float*)d_in[1];
    const float* goal   = (const float*)d_in[2];
    const float* L      = (const float*)d_in[3];
    const float* sdf    = (const float*)d_in[4];
    const float* minb   = (const float*)d_in[5];
    const int*   map_id = (const int*)d_in[6];
    float* out = (float*)d_out;

    const int outer = in_sizes[6];

    zero_out_kernel<<<(out_size + 255) / 256, 256>>>(out, out_size);
    dim3 grid(outer, NT);
    track_loss_kernel<<<grid, 256>>>(Df, Dp, goal, L, sdf, minb, map_id, out);
}

// round 4
// speedup vs baseline: 1.2154x; 1.1753x over previous
#include <cuda_runtime.h>
#include <cuda_bf16.h>

#define TRAJ      25
#define NT        10
#define NS        10
#define GDIM      200
#define MAP_ELEMS 8000000
#define VFOV_C    0.3490658503988659f
#define MAX_BT    (1024 * TRAJ * NT)   // supports outer up to 1024

// Staging buffers: voxel-space position & goal-direction per (b, t), pitch pen.
__device__ float g_pvx[MAX_BT];
__device__ float g_pvy[MAX_BT];
__device__ float g_pvz[MAX_BT];
__device__ float g_gvx[MAX_BT];
__device__ float g_gvy[MAX_BT];
__device__ float g_gvz[MAX_BT];
__device__ float g_pen[MAX_BT];

// ---------- kernel 1: per-(b,t) prelude ----------
__global__ __launch_bounds__(256) void prelude_kernel(
    const float* __restrict__ Df, const float* __restrict__ Dp,
    const float* __restrict__ goal, const float* __restrict__ L,
    const float* __restrict__ minb, const int* __restrict__ map_id,
    float* __restrict__ out, int n_bt)
{
    const int n = blockIdx.x * blockDim.x + threadIdx.x;
    if (n >= n_bt) return;
    const int b  = n / NT;
    const int it = n - b * NT;
    const int o  = b / TRAJ;

    const float t = 0.66f + (float)it * ((1.32f - 0.66f) / 9.0f);

    float pos[3], vel[3];
    #pragma unroll
    for (int c = 0; c < 3; c++) {
        const float d0 = __ldg(Df + b * 9 + c * 3 + 0);
        const float d1 = __ldg(Df + b * 9 + c * 3 + 1);
        const float d2 = __ldg(Df + b * 9 + c * 3 + 2);
        const float d3 = __ldg(Dp + b * 9 + c * 3 + 0);
        const float d4 = __ldg(Dp + b * 9 + c * 3 + 1);
        const float d5 = __ldg(Dp + b * 9 + c * 3 + 2);
        float coe[6];
        #pragma unroll
        for (int i = 0; i < 6; i++) {
            coe[i] = __ldg(L + i * 6 + 0) * d0 + __ldg(L + i * 6 + 1) * d1
                   + __ldg(L + i * 6 + 2) * d2 + __ldg(L + i * 6 + 3) * d3
                   + __ldg(L + i * 6 + 4) * d4 + __ldg(L + i * 6 + 5) * d5;
        }
        float p = coe[5];
        p = p * t + coe[4];
        p = p * t + coe[3];
        p = p * t + coe[2];
        p = p * t + coe[1];
        p = p * t + coe[0];
        pos[c] = p;
        float v = 5.0f * coe[5];
        v = v * t + 4.0f * coe[4];
        v = v * t + 3.0f * coe[3];
        v = v * t + 2.0f * coe[2];
        v = v * t + coe[1];
        vel[c] = v;
    }

    const float gx0 = __ldg(goal + (long long)o * TRAJ * 3 + 0);
    const float gy0 = __ldg(goal + (long long)o * TRAJ * 3 + 1);
    const float gz0 = __ldg(goal + (long long)o * TRAJ * 3 + 2);
    const float gdx = gx0 - pos[0];
    const float gdy = gy0 - pos[1];
    const float gdz = gz0 - pos[2];

    const float pg = atan2f(gdz, sqrtf(gdx * gdx + gdy * gdy + 1e-6f));
    const float pv = atan2f(vel[2], sqrtf(vel[0] * vel[0] + vel[1] * vel[1] + 1e-6f));
    g_pen[n] = fmaxf(fabsf(pg - pv) - VFOV_C, 0.0f);

    // pre-scale to voxel space: v = (pos - mb) / 0.2; LOS point = pv + a*gv
    const int   m   = __ldg(map_id + o);
    const float mb0 = __ldg(minb + m * 3 + 0);
    const float mb1 = __ldg(minb + m * 3 + 1);
    const float mb2 = __ldg(minb + m * 3 + 2);
    g_pvx[n] = (pos[0] - mb0) * 5.0f;
    g_pvy[n] = (pos[1] - mb1) * 5.0f;
    g_pvz[n] = (pos[2] - mb2) * 5.0f;
    g_gvx[n] = gdx * 5.0f;
    g_gvy[n] = gdy * 5.0f;
    g_gvz[n] = gdz * 5.0f;

    if (it == 0) out[b] = 0.0f;   // zero-init before gather kernel's atomics
}

// ---------- kernel 2: one trilinear SDF sample per thread ----------
// grid (outer, NS); thread tid<250 -> (traj j, time it). Warp lanes span
// consecutive t for the same trajectory -> coalesced corner gathers.
__global__ __launch_bounds__(256) void gather_kernel(
    const float* __restrict__ sdf, const int* __restrict__ map_id,
    float* __restrict__ out)
{
    const int o   = blockIdx.x;
    const int s   = blockIdx.y;
    const int tid = threadIdx.x;

    __shared__ float sC[TRAJ * NT];

    float w = 0.0f;
    if (tid < TRAJ * NT) {
        const int n = (o * TRAJ) * NT + tid;   // (b=o*TRAJ + tid/NT, it=tid%NT)

        const float a  = (float)s * (1.0f / 9.0f);
        const float vx = __ldg(g_pvx + n) + a * __ldg(g_gvx + n);
        const float vy = __ldg(g_pvy + n) + a * __ldg(g_gvy + n);
        const float vz = __ldg(g_pvz + n) + a * __ldg(g_gvz + n);

        const bool valid = (vx > 0.5f) && (vx < (float)GDIM - 1.5f)
                        && (vy > 0.5f) && (vy < (float)GDIM - 1.5f)
                        && (vz > 0.5f) && (vz < (float)GDIM - 1.5f);

        float cost = 0.0f;  // invalid -> relu(0.2-0)=0.2 contribution
        if (valid) {
            const float* __restrict__ map =
                sdf + (long long)__ldg(map_id + o) * MAP_ELEMS;
            const float x0f = fminf(fmaxf(floorf(vx), 0.0f), (float)(GDIM - 2));
            const float y0f = fminf(fmaxf(floorf(vy), 0.0f), (float)(GDIM - 2));
            const float z0f = fminf(fmaxf(floorf(vz), 0.0f), (float)(GDIM - 2));
            const float fx = vx - x0f, fy = vy - y0f, fz = vz - z0f;
            const int ix = (int)x0f, iy = (int)y0f, iz = (int)z0f;
            const int base = iz * (GDIM * GDIM) + iy * GDIM + ix;

            const float c000 = __ldg(map + base);
            const float c001 = __ldg(map + base + 1);
            const float c010 = __ldg(map + base + GDIM);
            const float c011 = __ldg(map + base + GDIM + 1);
            const float c100 = __ldg(map + base + GDIM * GDIM);
            const float c101 = __ldg(map + base + GDIM * GDIM + 1);
            const float c110 = __ldg(map + base + GDIM * GDIM + GDIM);
            const float c111 = __ldg(map + base + GDIM * GDIM + GDIM + 1);

            const float omx = 1.0f - fx, omy = 1.0f - fy;
            const float c0 = (c000 * omx + c001 * fx) * omy
                           + (c010 * omx + c011 * fx) * fy;
            const float c1 = (c100 * omx + c101 * fx) * omy
                           + (c110 * omx + c111 * fx) * fy;
            const float dist = c0 * (1.0f - fz) + c1 * fz;
            cost = __expf(-(dist - 0.6f) * (1.0f / 0.3f));
        }
        // out[b] = 0.2*sum_{t,s} relu + 0.5*sum_t pen ; this block covers one s
        w = 0.2f * fmaxf(0.2f - cost, 0.0f);
        if (s == 0) w += 0.5f * __ldg(g_pen + n);   // fold pitch term once
        sC[tid] = w;
    }
    __syncthreads();

    if (tid < TRAJ) {
        float v = 0.0f;
        #pragma unroll
        for (int k = 0; k < NT; k++) v += sC[tid * NT + k];
        atomicAdd(&out[o * TRAJ + tid], v);
    }
}

extern "C" void kernel_launch(void* const* d_in, const int* in_sizes, int n_in,
                              void* d_out, int out_size)
{
    const float* Df     = (const float*)d_in[0];
    const float* Dp     = (const float*)d_in[1];
    const float* goal   = (const float*)d_in[2];
    const float* L      = (const float*)d_in[3];
    const float* sdf    = (const float*)d_in[4];
    const float* minb   = (const float*)d_in[5];
    const int*   map_id = (const int*)d_in[6];
    float* out = (float*)d_out;

    const int outer = in_sizes[6];
    const int n_bt  = outer * TRAJ * NT;

    prelude_kernel<<<(n_bt + 255) / 256, 256>>>(Df, Dp, goal, L, minb, map_id,
                                                out, n_bt);
    dim3 grid(outer, NS);
    gather_kernel<<<grid, 256>>>(sdf, map_id, out);
}

// round 5
// speedup vs baseline: 1.2318x; 1.0135x over previous
#include <cuda_runtime.h>
#include <cuda_bf16.h>

#define TRAJ      25
#define NT        10
#define NS        10
#define GDIM      200
#define MAP_ELEMS 8000000
#define VFOV_C    0.3490658503988659f
#define MAX_BT    (1024 * TRAJ * NT)   // supports outer up to 1024

// Staging: voxel-space position & goal-direction per (b, t), pitch penalty.
__device__ float g_pvx[MAX_BT];
__device__ float g_pvy[MAX_BT];
__device__ float g_pvz[MAX_BT];
__device__ float g_gvx[MAX_BT];
__device__ float g_gvy[MAX_BT];
__device__ float g_gvz[MAX_BT];
__device__ float g_pen[MAX_BT];

// ---------- kernel 1: per-(b,t) prelude ----------
__global__ __launch_bounds__(256) void prelude_kernel(
    const float* __restrict__ Df, const float* __restrict__ Dp,
    const float* __restrict__ goal, const float* __restrict__ L,
    const float* __restrict__ minb, const int* __restrict__ map_id,
    float* __restrict__ out, int n_bt)
{
    const int n = blockIdx.x * blockDim.x + threadIdx.x;
    if (n >= n_bt) return;
    const int b  = n / NT;
    const int it = n - b * NT;
    const int o  = b / TRAJ;

    const float t = 0.66f + (float)it * ((1.32f - 0.66f) / 9.0f);

    float pos[3], vel[3];
    #pragma unroll
    for (int c = 0; c < 3; c++) {
        const float d0 = __ldg(Df + b * 9 + c * 3 + 0);
        const float d1 = __ldg(Df + b * 9 + c * 3 + 1);
        const float d2 = __ldg(Df + b * 9 + c * 3 + 2);
        const float d3 = __ldg(Dp + b * 9 + c * 3 + 0);
        const float d4 = __ldg(Dp + b * 9 + c * 3 + 1);
        const float d5 = __ldg(Dp + b * 9 + c * 3 + 2);
        float coe[6];
        #pragma unroll
        for (int i = 0; i < 6; i++) {
            coe[i] = __ldg(L + i * 6 + 0) * d0 + __ldg(L + i * 6 + 1) * d1
                   + __ldg(L + i * 6 + 2) * d2 + __ldg(L + i * 6 + 3) * d3
                   + __ldg(L + i * 6 + 4) * d4 + __ldg(L + i * 6 + 5) * d5;
        }
        float p = coe[5];
        p = p * t + coe[4];
        p = p * t + coe[3];
        p = p * t + coe[2];
        p = p * t + coe[1];
        p = p * t + coe[0];
        pos[c] = p;
        float v = 5.0f * coe[5];
        v = v * t + 4.0f * coe[4];
        v = v * t + 3.0f * coe[3];
        v = v * t + 2.0f * coe[2];
        v = v * t + coe[1];
        vel[c] = v;
    }

    const float gx0 = __ldg(goal + (long long)o * TRAJ * 3 + 0);
    const float gy0 = __ldg(goal + (long long)o * TRAJ * 3 + 1);
    const float gz0 = __ldg(goal + (long long)o * TRAJ * 3 + 2);
    const float gdx = gx0 - pos[0];
    const float gdy = gy0 - pos[1];
    const float gdz = gz0 - pos[2];

    const float pg = atan2f(gdz, sqrtf(gdx * gdx + gdy * gdy + 1e-6f));
    const float pv = atan2f(vel[2], sqrtf(vel[0] * vel[0] + vel[1] * vel[1] + 1e-6f));
    g_pen[n] = fmaxf(fabsf(pg - pv) - VFOV_C, 0.0f);

    const int   m   = __ldg(map_id + o);
    const float mb0 = __ldg(minb + m * 3 + 0);
    const float mb1 = __ldg(minb + m * 3 + 1);
    const float mb2 = __ldg(minb + m * 3 + 2);
    g_pvx[n] = (pos[0] - mb0) * 5.0f;
    g_pvy[n] = (pos[1] - mb1) * 5.0f;
    g_pvz[n] = (pos[2] - mb2) * 5.0f;
    g_gvx[n] = gdx * 5.0f;
    g_gvy[n] = gdy * 5.0f;
    g_gvz[n] = gdz * 5.0f;

    if (it == 0) out[b] = 0.0f;   // zero-init before gather kernel's atomics
}

// ---------- kernel 2: TWO trilinear SDF samples per thread ----------
// grid (outer, NS/2); thread tid<250 -> (traj j, time it); samples s, s+5.
// Warp lanes span consecutive t -> warp-level merging of corner gathers.
__global__ __launch_bounds__(256) void gather_kernel(
    const float* __restrict__ sdf, const int* __restrict__ map_id,
    float* __restrict__ out)
{
    const int o   = blockIdx.x;
    const int s0  = blockIdx.y;          // samples s0 and s0+5
    const int tid = threadIdx.x;

    __shared__ float sC[TRAJ * NT];

    float w = 0.0f;
    if (tid < TRAJ * NT) {
        const int n = (o * TRAJ) * NT + tid;

        const float px = __ldg(g_pvx + n), gx = __ldg(g_gvx + n);
        const float py = __ldg(g_pvy + n), gy = __ldg(g_gvy + n);
        const float pz = __ldg(g_pvz + n), gz = __ldg(g_gvz + n);

        const float* __restrict__ map =
            sdf + (long long)__ldg(map_id + o) * MAP_ELEMS;

        // --- compute both sample coordinates ---
        float vx[2], vy[2], vz[2];
        bool valid[2];
        float fx[2], fy[2], fz[2];
        int base[2];
        #pragma unroll
        for (int k = 0; k < 2; k++) {
            const float a = (float)(s0 + 5 * k) * (1.0f / 9.0f);
            vx[k] = px + a * gx;
            vy[k] = py + a * gy;
            vz[k] = pz + a * gz;
            valid[k] = (vx[k] > 0.5f) && (vx[k] < (float)GDIM - 1.5f)
                    && (vy[k] > 0.5f) && (vy[k] < (float)GDIM - 1.5f)
                    && (vz[k] > 0.5f) && (vz[k] < (float)GDIM - 1.5f);
            const float x0f = fminf(fmaxf(floorf(vx[k]), 0.0f), (float)(GDIM - 2));
            const float y0f = fminf(fmaxf(floorf(vy[k]), 0.0f), (float)(GDIM - 2));
            const float z0f = fminf(fmaxf(floorf(vz[k]), 0.0f), (float)(GDIM - 2));
            fx[k] = vx[k] - x0f; fy[k] = vy[k] - y0f; fz[k] = vz[k] - z0f;
            base[k] = (int)z0f * (GDIM * GDIM) + (int)y0f * GDIM + (int)x0f;
            if (!valid[k]) base[k] = 0;   // safe dummy address
        }

        // --- issue all 16 gathers (both samples) before consuming ---
        float c[2][8];
        #pragma unroll
        for (int k = 0; k < 2; k++) {
            c[k][0] = __ldg(map + base[k]);
            c[k][1] = __ldg(map + base[k] + 1);
            c[k][2] = __ldg(map + base[k] + GDIM);
            c[k][3] = __ldg(map + base[k] + GDIM + 1);
            c[k][4] = __ldg(map + base[k] + GDIM * GDIM);
            c[k][5] = __ldg(map + base[k] + GDIM * GDIM + 1);
            c[k][6] = __ldg(map + base[k] + GDIM * GDIM + GDIM);
            c[k][7] = __ldg(map + base[k] + GDIM * GDIM + GDIM + 1);
        }

        #pragma unroll
        for (int k = 0; k < 2; k++) {
            const float omx = 1.0f - fx[k], omy = 1.0f - fy[k];
            const float l0 = (c[k][0] * omx + c[k][1] * fx[k]) * omy
                           + (c[k][2] * omx + c[k][3] * fx[k]) * fy[k];
            const float l1 = (c[k][4] * omx + c[k][5] * fx[k]) * omy
                           + (c[k][6] * omx + c[k][7] * fx[k]) * fy[k];
            const float dist = l0 * (1.0f - fz[k]) + l1 * fz[k];
            float cost = valid[k] ? __expf(-(dist - 0.6f) * (1.0f / 0.3f)) : 0.0f;
            w += 0.2f * fmaxf(0.2f - cost, 0.0f);
        }

        if (s0 == 0) w += 0.5f * __ldg(g_pen + n);   // fold pitch term once
        sC[tid] = w;
    }
    __syncthreads();

    if (tid < TRAJ) {
        float v = 0.0f;
        #pragma unroll
        for (int k = 0; k < NT; k++) v += sC[tid * NT + k];
        atomicAdd(&out[o * TRAJ + tid], v);
    }
}

extern "C" void kernel_launch(void* const* d_in, const int* in_sizes, int n_in,
                              void* d_out, int out_size)
{
    const float* Df     = (const float*)d_in[0];
    const float* Dp     = (const float*)d_in[1];
    const float* goal   = (const float*)d_in[2];
    const float* L      = (const float*)d_in[3];
    const float* sdf    = (const float*)d_in[4];
    const float* minb   = (const float*)d_in[5];
    const int*   map_id = (const int*)d_in[6];
    float* out = (float*)d_out;

    const int outer = in_sizes[6];
    const int n_bt  = outer * TRAJ * NT;

    prelude_kernel<<<(n_bt + 255) / 256, 256>>>(Df, Dp, goal, L, minb, map_id,
                                                out, n_bt);
    dim3 grid(outer, NS / 2);
    gather_kernel<<<grid, 256>>>(sdf, map_id, out);
}

// round 6
// speedup vs baseline: 1.3814x; 1.1214x over previous
#include <cuda_runtime.h>
#include <cuda_bf16.h>

#define TRAJ      25
#define NT        10
#define NS        10
#define GDIM      200
#define MAP_ELEMS 8000000
#define VFOV_C    0.3490658503988659f
#define MAX_BT    (1024 * TRAJ * NT)   // supports outer up to 1024

// Staging: voxel-space position & goal-direction per (b, t), pitch penalty.
__device__ float g_pvx[MAX_BT];
__device__ float g_pvy[MAX_BT];
__device__ float g_pvz[MAX_BT];
__device__ float g_gvx[MAX_BT];
__device__ float g_gvy[MAX_BT];
__device__ float g_gvz[MAX_BT];
__device__ float g_pen[MAX_BT];

// ---------- kernel 1: per-(b,t) prelude ----------
__global__ __launch_bounds__(256) void prelude_kernel(
    const float* __restrict__ Df, const float* __restrict__ Dp,
    const float* __restrict__ goal, const float* __restrict__ L,
    const float* __restrict__ minb, const int* __restrict__ map_id,
    float* __restrict__ out, int n_bt)
{
    const int n = blockIdx.x * blockDim.x + threadIdx.x;
    if (n >= n_bt) return;
    const int b  = n / NT;
    const int it = n - b * NT;
    const int o  = b / TRAJ;

    const float t = 0.66f + (float)it * ((1.32f - 0.66f) / 9.0f);

    float pos[3], vel[3];
    #pragma unroll
    for (int c = 0; c < 3; c++) {
        const float d0 = __ldg(Df + b * 9 + c * 3 + 0);
        const float d1 = __ldg(Df + b * 9 + c * 3 + 1);
        const float d2 = __ldg(Df + b * 9 + c * 3 + 2);
        const float d3 = __ldg(Dp + b * 9 + c * 3 + 0);
        const float d4 = __ldg(Dp + b * 9 + c * 3 + 1);
        const float d5 = __ldg(Dp + b * 9 + c * 3 + 2);
        float coe[6];
        #pragma unroll
        for (int i = 0; i < 6; i++) {
            coe[i] = __ldg(L + i * 6 + 0) * d0 + __ldg(L + i * 6 + 1) * d1
                   + __ldg(L + i * 6 + 2) * d2 + __ldg(L + i * 6 + 3) * d3
                   + __ldg(L + i * 6 + 4) * d4 + __ldg(L + i * 6 + 5) * d5;
        }
        float p = coe[5];
        p = p * t + coe[4];
        p = p * t + coe[3];
        p = p * t + coe[2];
        p = p * t + coe[1];
        p = p * t + coe[0];
        pos[c] = p;
        float v = 5.0f * coe[5];
        v = v * t + 4.0f * coe[4];
        v = v * t + 3.0f * coe[3];
        v = v * t + 2.0f * coe[2];
        v = v * t + coe[1];
        vel[c] = v;
    }

    const float gx0 = __ldg(goal + (long long)o * TRAJ * 3 + 0);
    const float gy0 = __ldg(goal + (long long)o * TRAJ * 3 + 1);
    const float gz0 = __ldg(goal + (long long)o * TRAJ * 3 + 2);
    const float gdx = gx0 - pos[0];
    const float gdy = gy0 - pos[1];
    const float gdz = gz0 - pos[2];

    const float pg = atan2f(gdz, sqrtf(gdx * gdx + gdy * gdy + 1e-6f));
    const float pv = atan2f(vel[2], sqrtf(vel[0] * vel[0] + vel[1] * vel[1] + 1e-6f));
    g_pen[n] = fmaxf(fabsf(pg - pv) - VFOV_C, 0.0f);

    const int   m   = __ldg(map_id + o);
    const float mb0 = __ldg(minb + m * 3 + 0);
    const float mb1 = __ldg(minb + m * 3 + 1);
    const float mb2 = __ldg(minb + m * 3 + 2);
    g_pvx[n] = (pos[0] - mb0) * 5.0f;
    g_pvy[n] = (pos[1] - mb1) * 5.0f;
    g_pvz[n] = (pos[2] - mb2) * 5.0f;
    g_gvx[n] = gdx * 5.0f;
    g_gvy[n] = gdy * 5.0f;
    g_gvz[n] = gdz * 5.0f;

    if (it == 0) out[b] = 0.0f;   // zero-init before gather kernel's atomics
}

// ---------- kernel 2: TWO trilinear SDF samples per thread ----------
// grid (outer, NS/2); thread tid<250 -> (traj j, time it); samples s, s+5.
// __launch_bounds__(256, 2): allow up to 128 regs so all 16 gathers stay
// in flight simultaneously (R5 was clamped to 32 regs -> serialized loads).
__global__ __launch_bounds__(256, 2) void gather_kernel(
    const float* __restrict__ sdf, const int* __restrict__ map_id,
    float* __restrict__ out)
{
    const int o   = blockIdx.x;
    const int s0  = blockIdx.y;          // samples s0 and s0+5
    const int tid = threadIdx.x;

    __shared__ float sC[TRAJ * NT];

    float w = 0.0f;
    if (tid < TRAJ * NT) {
        const int n = (o * TRAJ) * NT + tid;

        const float px = __ldg(g_pvx + n), gx = __ldg(g_gvx + n);
        const float py = __ldg(g_pvy + n), gy = __ldg(g_gvy + n);
        const float pz = __ldg(g_pvz + n), gz = __ldg(g_gvz + n);

        const float* __restrict__ map =
            sdf + (long long)__ldg(map_id + o) * MAP_ELEMS;

        // --- compute both sample coordinates / bases first ---
        float fx[2], fy[2], fz[2];
        bool  valid[2];
        int   base[2];
        #pragma unroll
        for (int k = 0; k < 2; k++) {
            const float a  = (float)(s0 + 5 * k) * (1.0f / 9.0f);
            const float vx = px + a * gx;
            const float vy = py + a * gy;
            const float vz = pz + a * gz;
            valid[k] = (vx > 0.5f) && (vx < (float)GDIM - 1.5f)
                    && (vy > 0.5f) && (vy < (float)GDIM - 1.5f)
                    && (vz > 0.5f) && (vz < (float)GDIM - 1.5f);
            const float x0f = fminf(fmaxf(floorf(vx), 0.0f), (float)(GDIM - 2));
            const float y0f = fminf(fmaxf(floorf(vy), 0.0f), (float)(GDIM - 2));
            const float z0f = fminf(fmaxf(floorf(vz), 0.0f), (float)(GDIM - 2));
            fx[k] = vx - x0f; fy[k] = vy - y0f; fz[k] = vz - z0f;
            int bb = (int)z0f * (GDIM * GDIM) + (int)y0f * GDIM + (int)x0f;
            base[k] = valid[k] ? bb : 0;   // safe dummy address
        }

        // --- issue ALL 16 gathers back-to-back, consume afterwards ---
        float c00, c01, c02, c03, c04, c05, c06, c07;
        float c10, c11, c12, c13, c14, c15, c16, c17;
        {
            const int b0 = base[0], b1 = base[1];
            c00 = __ldg(map + b0);
            c01 = __ldg(map + b0 + 1);
            c02 = __ldg(map + b0 + GDIM);
            c03 = __ldg(map + b0 + GDIM + 1);
            c04 = __ldg(map + b0 + GDIM * GDIM);
            c05 = __ldg(map + b0 + GDIM * GDIM + 1);
            c06 = __ldg(map + b0 + GDIM * GDIM + GDIM);
            c07 = __ldg(map + b0 + GDIM * GDIM + GDIM + 1);
            c10 = __ldg(map + b1);
            c11 = __ldg(map + b1 + 1);
            c12 = __ldg(map + b1 + GDIM);
            c13 = __ldg(map + b1 + GDIM + 1);
            c14 = __ldg(map + b1 + GDIM * GDIM);
            c15 = __ldg(map + b1 + GDIM * GDIM + 1);
            c16 = __ldg(map + b1 + GDIM * GDIM + GDIM);
            c17 = __ldg(map + b1 + GDIM * GDIM + GDIM + 1);
        }

        {
            const float omx = 1.0f - fx[0], omy = 1.0f - fy[0];
            const float l0 = (c00 * omx + c01 * fx[0]) * omy
                           + (c02 * omx + c03 * fx[0]) * fy[0];
            const float l1 = (c04 * omx + c05 * fx[0]) * omy
                           + (c06 * omx + c07 * fx[0]) * fy[0];
            const float dist = l0 * (1.0f - fz[0]) + l1 * fz[0];
            const float cost = valid[0] ? __expf(-(dist - 0.6f) * (1.0f / 0.3f)) : 0.0f;
            w += 0.2f * fmaxf(0.2f - cost, 0.0f);
        }
        {
            const float omx = 1.0f - fx[1], omy = 1.0f - fy[1];
            const float l0 = (c10 * omx + c11 * fx[1]) * omy
                           + (c12 * omx + c13 * fx[1]) * fy[1];
            const float l1 = (c14 * omx + c15 * fx[1]) * omy
                           + (c16 * omx + c17 * fx[1]) * fy[1];
            const float dist = l0 * (1.0f - fz[1]) + l1 * fz[1];
            const float cost = valid[1] ? __expf(-(dist - 0.6f) * (1.0f / 0.3f)) : 0.0f;
            w += 0.2f * fmaxf(0.2f - cost, 0.0f);
        }

        if (s0 == 0) w += 0.5f * __ldg(g_pen + n);   // fold pitch term once
        sC[tid] = w;
    }
    __syncthreads();

    if (tid < TRAJ) {
        float v = 0.0f;
        #pragma unroll
        for (int k = 0; k < NT; k++) v += sC[tid * NT + k];
        atomicAdd(&out[o * TRAJ + tid], v);
    }
}

extern "C" void kernel_launch(void* const* d_in, const int* in_sizes, int n_in,
                              void* d_out, int out_size)
{
    const float* Df     = (const float*)d_in[0];
    const float* Dp     = (const float*)d_in[1];
    const float* goal   = (const float*)d_in[2];
    const float* L      = (const float*)d_in[3];
    const float* sdf    = (const float*)d_in[4];
    const float* minb   = (const float*)d_in[5];
    const int*   map_id = (const int*)d_in[6];
    float* out = (float*)d_out;

    const int outer = in_sizes[6];
    const int n_bt  = outer * TRAJ * NT;

    prelude_kernel<<<(n_bt + 255) / 256, 256>>>(Df, Dp, goal, L, minb, map_id,
                                                out, n_bt);
    dim3 grid(outer, NS / 2);
    gather_kernel<<<grid, 256>>>(sdf, map_id, out);
}